// round 3
// baseline (speedup 1.0000x reference)
#include <cuda_runtime.h>

#define Bp 32
#define Np 1024
#define Mp 1024
#define Dp 128

// Scratch (device globals: no allocation allowed in kernel_launch)
__device__ float g_Xc[Bp * Np * Dp];                 // 16 MB   X * tanh(W@A^T + b)
__device__ float g_P[(size_t)Bp * Np * Mp];          // 134 MB  1 + exp(z)  (unnormalized softmax weights)
__device__ float g_rs[Bp * Np];                      // row sums of P
__device__ float g_cs[Bp * Mp];                      // col sums of P

__device__ __forceinline__ unsigned long long fma2(unsigned long long a,
                                                   unsigned long long b,
                                                   unsigned long long c) {
    unsigned long long d;
    asm("fma.rn.f32x2 %0, %1, %2, %3;" : "=l"(d) : "l"(a), "l"(b), "l"(c));
    return d;
}

__device__ __forceinline__ float2 up2(unsigned long long u) {
    float2 f;
    asm("mov.b64 {%0, %1}, %2;" : "=f"(f.x), "=f"(f.y) : "l"(u));
    return f;
}

// ---------------------------------------------------------------------------
// K0: zero the softmax accumulators (graph replays need this every launch)
// ---------------------------------------------------------------------------
__global__ void k_zero() {
    int i = blockIdx.x * 256 + threadIdx.x;
    g_rs[i] = 0.f;
    g_cs[i] = 0.f;
}

// ---------------------------------------------------------------------------
// K1: Xc[r][e] = Xs[r][e] * tanh( sum_d W[r][d]*Aw[e][d] + Ab[e] )
// ---------------------------------------------------------------------------
__global__ __launch_bounds__(256) void k_coeff(const float* __restrict__ W,
                                               const float* __restrict__ Aw,
                                               const float* __restrict__ Ab,
                                               const float* __restrict__ Xs) {
    const int tx = threadIdx.x, ty = threadIdx.y;
    const int tid = ty * 16 + tx;
    const int r0 = blockIdx.x * 64;

    __shared__ __align__(16) float Ws[64][32];
    __shared__ __align__(16) float Awt[32][132];

    float acc[4][8];
#pragma unroll
    for (int i = 0; i < 4; i++)
#pragma unroll
        for (int j = 0; j < 8; j++) acc[i][j] = 0.f;

    for (int k0 = 0; k0 < Dp; k0 += 32) {
#pragma unroll
        for (int it = 0; it < 2; it++) {
            int id = tid + it * 256;
            int r = id >> 3, q = id & 7;
            *(float4*)&Ws[r][q * 4] =
                *(const float4*)(W + (size_t)(r0 + r) * Dp + k0 + q * 4);
        }
#pragma unroll
        for (int it = 0; it < 4; it++) {
            int id = tid + it * 256;
            int e = id >> 3, q = id & 7;
            float4 v = *(const float4*)(Aw + (size_t)e * Dp + k0 + q * 4);
            Awt[q * 4 + 0][e] = v.x;
            Awt[q * 4 + 1][e] = v.y;
            Awt[q * 4 + 2][e] = v.z;
            Awt[q * 4 + 3][e] = v.w;
        }
        __syncthreads();
#pragma unroll
        for (int k = 0; k < 32; k++) {
            float w0 = Ws[ty * 4 + 0][k];
            float w1 = Ws[ty * 4 + 1][k];
            float w2 = Ws[ty * 4 + 2][k];
            float w3 = Ws[ty * 4 + 3][k];
            float4 a0 = *(const float4*)&Awt[k][tx * 8];
            float4 a1 = *(const float4*)&Awt[k][tx * 8 + 4];
            float av[8] = {a0.x, a0.y, a0.z, a0.w, a1.x, a1.y, a1.z, a1.w};
#pragma unroll
            for (int j = 0; j < 8; j++) {
                acc[0][j] = fmaf(w0, av[j], acc[0][j]);
                acc[1][j] = fmaf(w1, av[j], acc[1][j]);
                acc[2][j] = fmaf(w2, av[j], acc[2][j]);
                acc[3][j] = fmaf(w3, av[j], acc[3][j]);
            }
        }
        __syncthreads();
    }

    float abv[8];
    *(float4*)&abv[0] = *(const float4*)(Ab + tx * 8);
    *(float4*)&abv[4] = *(const float4*)(Ab + tx * 8 + 4);

#pragma unroll
    for (int i = 0; i < 4; i++) {
        int r = r0 + ty * 4 + i;
        const float* xr = Xs + (size_t)r * Dp + tx * 8;
        float4 x0 = *(const float4*)xr;
        float4 x1 = *(const float4*)(xr + 4);
        float c[8];
#pragma unroll
        for (int j = 0; j < 8; j++) c[j] = tanhf(acc[i][j] + abv[j]);
        float4 o0 = make_float4(x0.x * c[0], x0.y * c[1], x0.z * c[2], x0.w * c[3]);
        float4 o1 = make_float4(x1.x * c[4], x1.y * c[5], x1.z * c[6], x1.w * c[7]);
        float* dst = g_Xc + (size_t)r * Dp + tx * 8;
        *(float4*)dst = o0;
        *(float4*)(dst + 4) = o1;
    }
}

// ---------------------------------------------------------------------------
// Shared inner-product micro-kernel: 8x8 per thread via FFMA2.
// ---------------------------------------------------------------------------
#define INNER_K(As2row, Bsrow)                                              \
    do {                                                                    \
        const ulonglong2* ap = (const ulonglong2*)&(As2row)[ty * 16];       \
        ulonglong2 a01 = ap[0], a23 = ap[1], a45 = ap[2], a67 = ap[3];      \
        const ulonglong2* bp = (const ulonglong2*)&(Bsrow)[tx * 8];         \
        ulonglong2 b01 = bp[0], b23 = bp[1];                                \
        unsigned long long av[8] = {a01.x, a01.y, a23.x, a23.y,             \
                                    a45.x, a45.y, a67.x, a67.y};            \
        unsigned long long bv[4] = {b01.x, b01.y, b23.x, b23.y};            \
        _Pragma("unroll") for (int i = 0; i < 8; i++)                       \
            _Pragma("unroll") for (int j = 0; j < 4; j++)                   \
                acc[i][j] = fma2(av[i], bv[j], acc[i][j]);                  \
    } while (0)

// ---------------------------------------------------------------------------
// K2: z = Xc @ Y^T; s = softplus(z)-0.5 (output); P = 1+e^z (scratch);
//     accumulate row/col sums of P. Double-buffered smem, k-chunk = 8.
// ---------------------------------------------------------------------------
__global__ __launch_bounds__(256, 2) void k_scores(const float* __restrict__ Ys,
                                                   float* __restrict__ out_s) {
    const int tx = threadIdx.x, ty = threadIdx.y;
    const int tid = ty * 16 + tx;
    const int mt = blockIdx.x, nt = blockIdx.y, b = blockIdx.z;

    __shared__ __align__(16) float As2[2][8][256];
    __shared__ __align__(16) float Bs[2][8][128];
    __shared__ float scs[128];

    unsigned long long acc[8][4];
#pragma unroll
    for (int i = 0; i < 8; i++)
#pragma unroll
        for (int j = 0; j < 4; j++) acc[i][j] = 0ULL;

    const float* Xc = g_Xc + (size_t)(b * Np + nt * 128) * Dp;
    const float* Yb = Ys + (size_t)(b * Mp + mt * 128) * Dp;
    const int n = tid >> 1, kq = tid & 1;

    if (tid < 128) scs[tid] = 0.f;

    // prologue: chunk 0
    {
        float4 va = *(const float4*)(Xc + (size_t)n * Dp + kq * 4);
        float4 vb = *(const float4*)(Yb + (size_t)n * Dp + kq * 4);
        ((float2*)&As2[0][kq * 4 + 0][0])[n] = make_float2(va.x, va.x);
        ((float2*)&As2[0][kq * 4 + 1][0])[n] = make_float2(va.y, va.y);
        ((float2*)&As2[0][kq * 4 + 2][0])[n] = make_float2(va.z, va.z);
        ((float2*)&As2[0][kq * 4 + 3][0])[n] = make_float2(va.w, va.w);
        Bs[0][kq * 4 + 0][n] = vb.x;
        Bs[0][kq * 4 + 1][n] = vb.y;
        Bs[0][kq * 4 + 2][n] = vb.z;
        Bs[0][kq * 4 + 3][n] = vb.w;
    }
    __syncthreads();

    const int NC = Dp / 8;  // 16
#pragma unroll 2
    for (int c = 0; c < NC; c++) {
        const int cur = c & 1;
        float4 pa, pb;
        const bool has = (c + 1 < NC);
        if (has) {
            pa = *(const float4*)(Xc + (size_t)n * Dp + (c + 1) * 8 + kq * 4);
            pb = *(const float4*)(Yb + (size_t)n * Dp + (c + 1) * 8 + kq * 4);
        }
#pragma unroll
        for (int k = 0; k < 8; k++) INNER_K(As2[cur][k], Bs[cur][k]);
        if (has) {
            const int nx = cur ^ 1;
            ((float2*)&As2[nx][kq * 4 + 0][0])[n] = make_float2(pa.x, pa.x);
            ((float2*)&As2[nx][kq * 4 + 1][0])[n] = make_float2(pa.y, pa.y);
            ((float2*)&As2[nx][kq * 4 + 2][0])[n] = make_float2(pa.z, pa.z);
            ((float2*)&As2[nx][kq * 4 + 3][0])[n] = make_float2(pa.w, pa.w);
            Bs[nx][kq * 4 + 0][n] = pb.x;
            Bs[nx][kq * 4 + 1][n] = pb.y;
            Bs[nx][kq * 4 + 2][n] = pb.z;
            Bs[nx][kq * 4 + 3][n] = pb.w;
        }
        __syncthreads();
    }

    // epilogue: s, P, row sums (warp shuffle), col sums (low-contention atomics)
    const size_t sbase =
        ((size_t)(b * Np + nt * 128 + ty * 8)) * Mp + mt * 128 + tx * 8;

    float csum[8];
#pragma unroll
    for (int j = 0; j < 8; j++) csum[j] = 0.f;

#pragma unroll
    for (int i = 0; i < 8; i++) {
        float sv[8], pv[8];
        float rs = 0.f;
#pragma unroll
        for (int j = 0; j < 4; j++) {
            float2 z = up2(acc[i][j]);
            float p0 = 1.f + __expf(z.x);
            float p1 = 1.f + __expf(z.y);
            sv[2 * j] = __logf(p0) - 0.5f;      // softplus(z) - 0.5
            sv[2 * j + 1] = __logf(p1) - 0.5f;
            pv[2 * j] = p0;
            pv[2 * j + 1] = p1;
            rs += p0 + p1;
            csum[2 * j] += p0;
            csum[2 * j + 1] += p1;
        }
        size_t off = sbase + (size_t)i * Mp;
        *(float4*)(out_s + off) = make_float4(sv[0], sv[1], sv[2], sv[3]);
        *(float4*)(out_s + off + 4) = make_float4(sv[4], sv[5], sv[6], sv[7]);
        *(float4*)(g_P + off) = make_float4(pv[0], pv[1], pv[2], pv[3]);
        *(float4*)(g_P + off + 4) = make_float4(pv[4], pv[5], pv[6], pv[7]);

        // reduce rs across the 16 tx lanes (intra-warp-half)
        rs += __shfl_xor_sync(0xFFFFFFFFu, rs, 1);
        rs += __shfl_xor_sync(0xFFFFFFFFu, rs, 2);
        rs += __shfl_xor_sync(0xFFFFFFFFu, rs, 4);
        rs += __shfl_xor_sync(0xFFFFFFFFu, rs, 8);
        if (tx == 0) atomicAdd(&g_rs[b * Np + nt * 128 + ty * 8 + i], rs);
    }

#pragma unroll
    for (int j = 0; j < 8; j++) atomicAdd(&scs[tx * 8 + j], csum[j]);
    __syncthreads();
    if (tid < 128) atomicAdd(&g_cs[b * Mp + mt * 128 + tid], scs[tid]);
}

// ---------------------------------------------------------------------------
// K3 (merged): mode 0 -> attention_x[n][d] = sum_m P[n][m] Y[m][d] / rowsum[n]
//              mode 1 -> attention_y[m][d] = sum_n P[n][m] X[n][d] / colsum[m]
// Double-buffered smem, k-chunk = 8, grid (8 tiles, 2*B).
// ---------------------------------------------------------------------------
__global__ __launch_bounds__(256, 2) void k_attn(const float* __restrict__ Xs,
                                                 const float* __restrict__ Ys,
                                                 float* __restrict__ out_x,
                                                 float* __restrict__ out_y) {
    const int tx = threadIdx.x, ty = threadIdx.y;
    const int tid = ty * 16 + tx;
    const int rt = blockIdx.x;          // row-tile (128 output rows)
    const int b = blockIdx.y >> 1;
    const int mode = blockIdx.y & 1;

    __shared__ __align__(16) float As2[2][8][256];
    __shared__ __align__(16) float Bs[2][8][128];

    unsigned long long acc[8][4];
#pragma unroll
    for (int i = 0; i < 8; i++)
#pragma unroll
        for (int j = 0; j < 4; j++) acc[i][j] = 0ULL;

    const float* Pb = g_P + (size_t)b * Np * Mp;
    const float* Bsrc =
        mode ? (Xs + (size_t)b * Np * Dp) : (Ys + (size_t)b * Mp * Dp);
    const int n = tid >> 1, kq = tid & 1;   // mode-0 A load
    const int kr = tid >> 5, dq = tid & 31; // B load & mode-1 A load

    // prologue chunk 0
    {
        if (mode == 0) {
            float4 va = *(const float4*)(Pb + (size_t)(rt * 128 + n) * Mp + kq * 4);
            ((float2*)&As2[0][kq * 4 + 0][0])[n] = make_float2(va.x, va.x);
            ((float2*)&As2[0][kq * 4 + 1][0])[n] = make_float2(va.y, va.y);
            ((float2*)&As2[0][kq * 4 + 2][0])[n] = make_float2(va.z, va.z);
            ((float2*)&As2[0][kq * 4 + 3][0])[n] = make_float2(va.w, va.w);
        } else {
            float4 va = *(const float4*)(Pb + (size_t)kr * Mp + rt * 128 + dq * 4);
            ((float2*)&As2[0][kr][0])[dq * 4 + 0] = make_float2(va.x, va.x);
            ((float2*)&As2[0][kr][0])[dq * 4 + 1] = make_float2(va.y, va.y);
            ((float2*)&As2[0][kr][0])[dq * 4 + 2] = make_float2(va.z, va.z);
            ((float2*)&As2[0][kr][0])[dq * 4 + 3] = make_float2(va.w, va.w);
        }
        *(float4*)&Bs[0][kr][dq * 4] =
            *(const float4*)(Bsrc + (size_t)kr * Dp + dq * 4);
    }
    __syncthreads();

    const int NC = Mp / 8;  // 128
#pragma unroll 2
    for (int c = 0; c < NC; c++) {
        const int cur = c & 1;
        float4 pa, pb;
        const bool has = (c + 1 < NC);
        if (has) {
            const int k0 = (c + 1) * 8;
            if (mode == 0)
                pa = *(const float4*)(Pb + (size_t)(rt * 128 + n) * Mp + k0 + kq * 4);
            else
                pa = *(const float4*)(Pb + (size_t)(k0 + kr) * Mp + rt * 128 + dq * 4);
            pb = *(const float4*)(Bsrc + (size_t)(k0 + kr) * Dp + dq * 4);
        }
#pragma unroll
        for (int k = 0; k < 8; k++) INNER_K(As2[cur][k], Bs[cur][k]);
        if (has) {
            const int nx = cur ^ 1;
            if (mode == 0) {
                ((float2*)&As2[nx][kq * 4 + 0][0])[n] = make_float2(pa.x, pa.x);
                ((float2*)&As2[nx][kq * 4 + 1][0])[n] = make_float2(pa.y, pa.y);
                ((float2*)&As2[nx][kq * 4 + 2][0])[n] = make_float2(pa.z, pa.z);
                ((float2*)&As2[nx][kq * 4 + 3][0])[n] = make_float2(pa.w, pa.w);
            } else {
                ((float2*)&As2[nx][kr][0])[dq * 4 + 0] = make_float2(pa.x, pa.x);
                ((float2*)&As2[nx][kr][0])[dq * 4 + 1] = make_float2(pa.y, pa.y);
                ((float2*)&As2[nx][kr][0])[dq * 4 + 2] = make_float2(pa.z, pa.z);
                ((float2*)&As2[nx][kr][0])[dq * 4 + 3] = make_float2(pa.w, pa.w);
            }
            *(float4*)&Bs[nx][kr][dq * 4] = pb;
        }
        __syncthreads();
    }

    const float* norm = mode ? &g_cs[b * Mp + rt * 128] : &g_rs[b * Np + rt * 128];
    float* outp = mode ? (out_y + (size_t)b * Mp * Dp) : (out_x + (size_t)b * Np * Dp);

    float inv[8];
#pragma unroll
    for (int i = 0; i < 8; i++) inv[i] = 1.0f / norm[ty * 8 + i];

#pragma unroll
    for (int i = 0; i < 8; i++) {
        float o[8];
#pragma unroll
        for (int j = 0; j < 4; j++) {
            float2 v = up2(acc[i][j]);
            o[2 * j] = v.x * inv[i];
            o[2 * j + 1] = v.y * inv[i];
        }
        size_t off = (size_t)(rt * 128 + ty * 8 + i) * Dp + tx * 8;
        *(float4*)(outp + off) = make_float4(o[0], o[1], o[2], o[3]);
        *(float4*)(outp + off + 4) = make_float4(o[4], o[5], o[6], o[7]);
    }
}

// ---------------------------------------------------------------------------
extern "C" void kernel_launch(void* const* d_in, const int* in_sizes, int n_in,
                              void* d_out, int out_size) {
    const float* Xs = (const float*)d_in[0];
    const float* Ys = (const float*)d_in[1];
    const float* W  = (const float*)d_in[2];
    const float* Aw = (const float*)d_in[3];
    const float* Ab = (const float*)d_in[4];

    float* out = (float*)d_out;
    float* out_x = out;                                  // [B,N,D]
    float* out_y = out_x + (size_t)Bp * Np * Dp;         // [B,M,D]
    float* out_s = out_y + (size_t)Bp * Mp * Dp;         // [B,N,M]

    k_zero<<<(Bp * Np) / 256, 256>>>();
    k_coeff<<<(Bp * Np) / 64, dim3(16, 16)>>>(W, Aw, Ab, Xs);
    k_scores<<<dim3(Mp / 128, Np / 128, Bp), dim3(16, 16)>>>(Ys, out_s);
    k_attn<<<dim3(Np / 128, 2 * Bp), dim3(16, 16)>>>(Xs, Ys, out_x, out_y);
}

// round 5
// speedup vs baseline: 1.3958x; 1.3958x over previous
#include <cuda_runtime.h>
#include <mma.h>
#include <cstdint>

using namespace nvcuda;

#define Bp 32
#define Np 1024
#define Mp 1024
#define Dp 128

// Scratch (device globals; allocation is forbidden everywhere)
__device__ float g_Xc[Bp * Np * Dp];            // X * tanh(W@A^T+b)  [b][n][d]
__device__ float g_P[(size_t)Bp * Np * Mp];     // P = 1+e^z          [b][n][m]
__device__ float g_rs[Bp * Np];                 // row sums of P
__device__ float g_cs[Bp * Mp];                 // col sums of P

// ---------------------------------------------------------------------------
__device__ __forceinline__ uint32_t s2u(const void* p) {
    uint32_t a;
    asm("{ .reg .u64 t; cvta.to.shared.u64 t, %1; cvt.u32.u64 %0, t; }"
        : "=r"(a) : "l"(p));
    return a;
}
__device__ __forceinline__ void cpa16(uint32_t d, const void* s) {
    asm volatile("cp.async.cg.shared.global [%0], [%1], 16;"
                 :: "r"(d), "l"(s) : "memory");
}
#define CP_COMMIT() asm volatile("cp.async.commit_group;" ::: "memory")
#define CP_WAIT1()  asm volatile("cp.async.wait_group 1;" ::: "memory")
#define CP_WAIT0()  asm volatile("cp.async.wait_group 0;" ::: "memory")

// smem layout (floats): buf f: A @ f*8704, B @ f*8704+4352.  Epilogue: [128][132] @ 0.
#define BUFSZ 8704
#define SMEM_DYN 69632

typedef wmma::fragment<wmma::matrix_a, 16, 16, 8, wmma::precision::tf32,
                       wmma::row_major> FragAR;
typedef wmma::fragment<wmma::matrix_a, 16, 16, 8, wmma::precision::tf32,
                       wmma::col_major> FragAC;
typedef wmma::fragment<wmma::matrix_b, 16, 16, 8, wmma::precision::tf32,
                       wmma::row_major> FragBR;
typedef wmma::fragment<wmma::matrix_b, 16, 16, 8, wmma::precision::tf32,
                       wmma::col_major> FragBC;
typedef wmma::fragment<wmma::accumulator, 16, 16, 8, float> FragC;

template <class F>
__device__ __forceinline__ void cvt_tf32(F& f) {
#pragma unroll
    for (int e = 0; e < f.num_elements; e++)
        f.x[e] = wmma::__float_to_tf32(f.x[e]);
}

// ---------------------------------------------------------------------------
__global__ void k_zero() {
    int i = blockIdx.x * 256 + threadIdx.x;
    g_rs[i] = 0.f;
    g_cs[i] = 0.f;
}

// ---------------------------------------------------------------------------
// K1: Xc[r][e] = Xs[r][e] * tanh( sum_d W[r][d]*Aw[e][d] + Ab[e] )  (verified)
// ---------------------------------------------------------------------------
__global__ __launch_bounds__(256) void k_coeff(const float* __restrict__ W,
                                               const float* __restrict__ Aw,
                                               const float* __restrict__ Ab,
                                               const float* __restrict__ Xs) {
    const int tx = threadIdx.x, ty = threadIdx.y;
    const int tid = ty * 16 + tx;
    const int r0 = blockIdx.x * 64;

    __shared__ __align__(16) float Ws[64][32];
    __shared__ __align__(16) float Awt[32][132];

    float acc[4][8];
#pragma unroll
    for (int i = 0; i < 4; i++)
#pragma unroll
        for (int j = 0; j < 8; j++) acc[i][j] = 0.f;

    for (int k0 = 0; k0 < Dp; k0 += 32) {
#pragma unroll
        for (int it = 0; it < 2; it++) {
            int id = tid + it * 256;
            int r = id >> 3, q = id & 7;
            *(float4*)&Ws[r][q * 4] =
                *(const float4*)(W + (size_t)(r0 + r) * Dp + k0 + q * 4);
        }
#pragma unroll
        for (int it = 0; it < 4; it++) {
            int id = tid + it * 256;
            int e = id >> 3, q = id & 7;
            float4 v = *(const float4*)(Aw + (size_t)e * Dp + k0 + q * 4);
            Awt[q * 4 + 0][e] = v.x;
            Awt[q * 4 + 1][e] = v.y;
            Awt[q * 4 + 2][e] = v.z;
            Awt[q * 4 + 3][e] = v.w;
        }
        __syncthreads();
#pragma unroll
        for (int k = 0; k < 32; k++) {
            float w0 = Ws[ty * 4 + 0][k];
            float w1 = Ws[ty * 4 + 1][k];
            float w2 = Ws[ty * 4 + 2][k];
            float w3 = Ws[ty * 4 + 3][k];
            float4 a0 = *(const float4*)&Awt[k][tx * 8];
            float4 a1 = *(const float4*)&Awt[k][tx * 8 + 4];
            float av[8] = {a0.x, a0.y, a0.z, a0.w, a1.x, a1.y, a1.z, a1.w};
#pragma unroll
            for (int j = 0; j < 8; j++) {
                acc[0][j] = fmaf(w0, av[j], acc[0][j]);
                acc[1][j] = fmaf(w1, av[j], acc[1][j]);
                acc[2][j] = fmaf(w2, av[j], acc[2][j]);
                acc[3][j] = fmaf(w3, av[j], acc[3][j]);
            }
        }
        __syncthreads();
    }

    float abv[8];
    *(float4*)&abv[0] = *(const float4*)(Ab + tx * 8);
    *(float4*)&abv[4] = *(const float4*)(Ab + tx * 8 + 4);

#pragma unroll
    for (int i = 0; i < 4; i++) {
        int r = r0 + ty * 4 + i;
        const float* xr = Xs + (size_t)r * Dp + tx * 8;
        float4 x0 = *(const float4*)xr;
        float4 x1 = *(const float4*)(xr + 4);
        float c[8];
#pragma unroll
        for (int j = 0; j < 8; j++) c[j] = tanhf(acc[i][j] + abv[j]);
        float4 o0 = make_float4(x0.x * c[0], x0.y * c[1], x0.z * c[2], x0.w * c[3]);
        float4 o1 = make_float4(x1.x * c[4], x1.y * c[5], x1.z * c[6], x1.w * c[7]);
        float* dst = g_Xc + (size_t)r * Dp + tx * 8;
        *(float4*)dst = o0;
        *(float4*)(dst + 4) = o1;
    }
}

// ---------------------------------------------------------------------------
// K2 (wmma tf32): z = Xc @ Y^T; writes s and P; accumulates row/col sums.
// CTA 128x128, K=128 in 4 chunks of 32, cp.async double buffer.
// ---------------------------------------------------------------------------
__global__ __launch_bounds__(256, 2) void k_scores(const float* __restrict__ Ys,
                                                   float* __restrict__ out_s) {
    extern __shared__ __align__(16) float smf[];
    const uint32_t sb = s2u(smf);
    const int t = threadIdx.x;
    const int w = t >> 5;
    const int mt = blockIdx.x, nt = blockIdx.y, b = blockIdx.z;

    const float* Ar = g_Xc + (size_t)(b * Np + nt * 128) * Dp;  // [128][128]
    const float* Br = Ys + (size_t)(b * Mp + mt * 128) * Dp;    // [128][128]

    const int m0 = (w >> 1) * 32, n0 = (w & 1) * 64;

    FragC acc[2][4];
#pragma unroll
    for (int i = 0; i < 2; i++)
#pragma unroll
        for (int j = 0; j < 4; j++) wmma::fill_fragment(acc[i][j], 0.f);

    // loader: chunk c -> buffer f. smem A[s][128][8], B[s][128][8] (s = k/8)
    auto load_chunk = [&](int c, int f) {
        uint32_t Ad = sb + (uint32_t)(f * BUFSZ) * 4;
        uint32_t Bd = Ad + 4352 * 4;
#pragma unroll
        for (int i = 0; i < 4; i++) {
            int id = t + i * 256;
            int m = id >> 3, q = id & 7;
            uint32_t doff = (uint32_t)((((q >> 1) * 128 + m) * 8 + (q & 1) * 4) * 4);
            cpa16(Ad + doff, Ar + (size_t)m * Dp + c * 32 + q * 4);
            cpa16(Bd + doff, Br + (size_t)m * Dp + c * 32 + q * 4);
        }
        CP_COMMIT();
    };

    load_chunk(0, 0);
    const int NC = 4;
    for (int c = 0; c < NC; c++) {
        if (c + 1 < NC) load_chunk(c + 1, (c + 1) & 1);
        if (c + 1 < NC) CP_WAIT1(); else CP_WAIT0();
        __syncthreads();
        const float* As = smf + (c & 1) * BUFSZ;
        const float* Bs = As + 4352;
#pragma unroll
        for (int s = 0; s < 4; s++) {
            FragAR af[2];
            FragBC bf[4];
#pragma unroll
            for (int i = 0; i < 2; i++) {
                wmma::load_matrix_sync(af[i], As + s * 1024 + (m0 + i * 16) * 8, 8);
                cvt_tf32(af[i]);
            }
#pragma unroll
            for (int j = 0; j < 4; j++) {
                wmma::load_matrix_sync(bf[j], Bs + s * 1024 + (n0 + j * 16) * 8, 8);
                cvt_tf32(bf[j]);
            }
#pragma unroll
            for (int i = 0; i < 2; i++)
#pragma unroll
                for (int j = 0; j < 4; j++)
                    wmma::mma_sync(acc[i][j], af[i], bf[j], acc[i][j]);
        }
        __syncthreads();
    }

    // stash accumulators to smem [128][132]
#pragma unroll
    for (int i = 0; i < 2; i++)
#pragma unroll
        for (int j = 0; j < 4; j++)
            wmma::store_matrix_sync(smf + (m0 + i * 16) * 132 + (n0 + j * 16),
                                    acc[i][j], 132, wmma::mem_row_major);
    __syncthreads();

    // pass 1: rows (coalesced). s out, P out, row sums; overwrite smem with P.
    {
        const int r = t >> 1, h = t & 1;
        float* rowp = smf + r * 132 + h * 64;
        float* sp = out_s + (size_t)(b * Np + nt * 128 + r) * Mp + mt * 128 + h * 64;
        float* pp = g_P + (size_t)(b * Np + nt * 128 + r) * Mp + mt * 128 + h * 64;
        float rs = 0.f;
#pragma unroll
        for (int j = 0; j < 16; j++) {
            float4 z = *(float4*)(rowp + j * 4);
            float4 P, S;
            P.x = 1.f + __expf(z.x); S.x = __logf(P.x) - 0.5f;
            P.y = 1.f + __expf(z.y); S.y = __logf(P.y) - 0.5f;
            P.z = 1.f + __expf(z.z); S.z = __logf(P.z) - 0.5f;
            P.w = 1.f + __expf(z.w); S.w = __logf(P.w) - 0.5f;
            rs += P.x + P.y + P.z + P.w;
            *(float4*)(sp + j * 4) = S;
            *(float4*)(pp + j * 4) = P;
            *(float4*)(rowp + j * 4) = P;
        }
        rs += __shfl_xor_sync(0xFFFFFFFFu, rs, 1);
        if (h == 0) atomicAdd(&g_rs[b * Np + nt * 128 + r], rs);
    }
    __syncthreads();

    // pass 2: column sums (lane-contiguous -> conflict-free)
    if (t < 128) {
        float cs = 0.f;
#pragma unroll 4
        for (int r = 0; r < 128; r++) cs += smf[r * 132 + t];
        atomicAdd(&g_cs[b * Mp + mt * 128 + t], cs);
    }
}

// ---------------------------------------------------------------------------
// K3 (wmma tf32, merged):
//  mode 0: attn_x[n][d] = sum_m P[n][m] Y[m][d] / rs[n]   (A row-major)
//  mode 1: attn_y[m][d] = sum_n P[n][m] X[n][d] / cs[m]   (A col-major)
// CTA 128 rows x 128 (=D) cols, K=1024 in 32 chunks of 32.
// ---------------------------------------------------------------------------
__global__ __launch_bounds__(256, 2) void k_attn(const float* __restrict__ Xs,
                                                 const float* __restrict__ Ys,
                                                 float* __restrict__ out_x,
                                                 float* __restrict__ out_y) {
    extern __shared__ __align__(16) float smf[];
    const uint32_t sb = s2u(smf);
    const int t = threadIdx.x;
    const int w = t >> 5;
    const int rt = blockIdx.x;
    const int b = blockIdx.y >> 1;
    const int mode = blockIdx.y & 1;

    const float* Pb = g_P + (size_t)b * Np * Mp;
    const float* Bsrc = mode ? (Xs + (size_t)b * Np * Dp)
                             : (Ys + (size_t)b * Mp * Dp);

    const int m0 = (w >> 1) * 32, n0 = (w & 1) * 64;

    FragC acc[2][4];
#pragma unroll
    for (int i = 0; i < 2; i++)
#pragma unroll
        for (int j = 0; j < 4; j++) wmma::fill_fragment(acc[i][j], 0.f);

    // loaders. B: [32][132] rows=k, cols=d. A mode0: [4][128][8]; mode1: [32][132].
    auto load_chunk = [&](int c, int f) {
        uint32_t Ad = sb + (uint32_t)(f * BUFSZ) * 4;
        uint32_t Bd = Ad + 4352 * 4;
        if (mode == 0) {
#pragma unroll
            for (int i = 0; i < 4; i++) {
                int id = t + i * 256;
                int m = id >> 3, q = id & 7;
                uint32_t doff =
                    (uint32_t)((((q >> 1) * 128 + m) * 8 + (q & 1) * 4) * 4);
                cpa16(Ad + doff,
                      Pb + (size_t)(rt * 128 + m) * Mp + c * 32 + q * 4);
            }
        } else {
#pragma unroll
            for (int i = 0; i < 4; i++) {
                int id = t + i * 256;
                int kr = id >> 5, dq = id & 31;
                cpa16(Ad + (uint32_t)((kr * 132 + dq * 4) * 4),
                      Pb + (size_t)(c * 32 + kr) * Mp + rt * 128 + dq * 4);
            }
        }
#pragma unroll
        for (int i = 0; i < 4; i++) {
            int id = t + i * 256;
            int kr = id >> 5, dq = id & 31;
            cpa16(Bd + (uint32_t)((kr * 132 + dq * 4) * 4),
                  Bsrc + (size_t)(c * 32 + kr) * Dp + dq * 4);
        }
        CP_COMMIT();
    };

    load_chunk(0, 0);
    const int NC = 32;
    for (int c = 0; c < NC; c++) {
        if (c + 1 < NC) load_chunk(c + 1, (c + 1) & 1);
        if (c + 1 < NC) CP_WAIT1(); else CP_WAIT0();
        __syncthreads();
        const float* As = smf + (c & 1) * BUFSZ;
        const float* Bs = As + 4352;
        if (mode == 0) {
#pragma unroll
            for (int s = 0; s < 4; s++) {
                FragAR af[2];
                FragBR bf[4];
#pragma unroll
                for (int i = 0; i < 2; i++) {
                    wmma::load_matrix_sync(af[i], As + s * 1024 + (m0 + i * 16) * 8, 8);
                    cvt_tf32(af[i]);
                }
#pragma unroll
                for (int j = 0; j < 4; j++) {
                    wmma::load_matrix_sync(bf[j], Bs + s * 8 * 132 + n0 + j * 16, 132);
                    cvt_tf32(bf[j]);
                }
#pragma unroll
                for (int i = 0; i < 2; i++)
#pragma unroll
                    for (int j = 0; j < 4; j++)
                        wmma::mma_sync(acc[i][j], af[i], bf[j], acc[i][j]);
            }
        } else {
#pragma unroll
            for (int s = 0; s < 4; s++) {
                FragAC af[2];
                FragBR bf[4];
#pragma unroll
                for (int i = 0; i < 2; i++) {
                    wmma::load_matrix_sync(af[i], As + s * 8 * 132 + m0 + i * 16, 132);
                    cvt_tf32(af[i]);
                }
#pragma unroll
                for (int j = 0; j < 4; j++) {
                    wmma::load_matrix_sync(bf[j], Bs + s * 8 * 132 + n0 + j * 16, 132);
                    cvt_tf32(bf[j]);
                }
#pragma unroll
                for (int i = 0; i < 2; i++)
#pragma unroll
                    for (int j = 0; j < 4; j++)
                        wmma::mma_sync(acc[i][j], af[i], bf[j], acc[i][j]);
            }
        }
        __syncthreads();
    }

    // stash to smem, then normalized coalesced write-out
#pragma unroll
    for (int i = 0; i < 2; i++)
#pragma unroll
        for (int j = 0; j < 4; j++)
            wmma::store_matrix_sync(smf + (m0 + i * 16) * 132 + (n0 + j * 16),
                                    acc[i][j], 132, wmma::mem_row_major);
    __syncthreads();

    {
        const int r = t >> 1, h = t & 1;
        const float inv =
            1.f / (mode ? g_cs[b * Mp + rt * 128 + r]
                        : g_rs[b * Np + rt * 128 + r]);
        const float* rowp = smf + r * 132 + h * 64;
        float* outp = (mode ? out_y : out_x) +
                      (size_t)(b * 1024 + rt * 128 + r) * Dp + h * 64;
#pragma unroll
        for (int j = 0; j < 16; j++) {
            float4 v = *(const float4*)(rowp + j * 4);
            *(float4*)(outp + j * 4) =
                make_float4(v.x * inv, v.y * inv, v.z * inv, v.w * inv);
        }
    }
}

// ---------------------------------------------------------------------------
extern "C" void kernel_launch(void* const* d_in, const int* in_sizes, int n_in,
                              void* d_out, int out_size) {
    const float* Xs = (const float*)d_in[0];
    const float* Ys = (const float*)d_in[1];
    const float* W  = (const float*)d_in[2];
    const float* Aw = (const float*)d_in[3];
    const float* Ab = (const float*)d_in[4];

    float* out = (float*)d_out;
    float* out_x = out;                               // [B,N,D]
    float* out_y = out_x + (size_t)Bp * Np * Dp;      // [B,M,D]
    float* out_s = out_y + (size_t)Bp * Mp * Dp;      // [B,N,M]

    cudaFuncSetAttribute(k_scores, cudaFuncAttributeMaxDynamicSharedMemorySize,
                         SMEM_DYN);
    cudaFuncSetAttribute(k_attn, cudaFuncAttributeMaxDynamicSharedMemorySize,
                         SMEM_DYN);

    k_zero<<<128, 256>>>();
    k_coeff<<<(Bp * Np) / 64, dim3(16, 16)>>>(W, Aw, Ab, Xs);
    k_scores<<<dim3(8, 8, 32), 256, SMEM_DYN>>>(Ys, out_s);
    k_attn<<<dim3(8, 64), 256, SMEM_DYN>>>(Xs, Ys, out_x, out_y);
}